// round 6
// baseline (speedup 1.0000x reference)
#include <cuda_runtime.h>
#include <cstdint>

// Problem constants
#define B_ROWS 8192
#define SEQ    512
#define HDIM   256
#define TH     768          // 3*H
#define POUT   96

// Tiling
#define TILE_B        64
#define NCTA          (B_ROWS / TILE_B)   // 128
#define NTHREADS      256
#define NWARPS        8
#define ROWS_PER_WARP 8                   // TILE_B / NWARPS
#define HSTR          72                  // padded row stride of h buffer ([k][row])
#define HBUF          (HDIM * HSTR)       // floats per h buffer

// Scratch: transposed weights (written by pre-kernel each call; deterministic)
__device__ __align__(16) float g_Wt[HDIM * TH];      // Wt[k][3H] = W_hh[j][k]
__device__ __align__(16) float g_WoutT[HDIM * POUT]; // WoutT[k][p] = W_out[p][k]

// ---------------- packed f32x2 helpers ----------------
__device__ __forceinline__ void fma2(unsigned long long& d,
                                     unsigned long long a,
                                     unsigned long long b) {
    asm("fma.rn.f32x2 %0, %1, %2, %0;" : "+l"(d) : "l"(a), "l"(b));
}
__device__ __forceinline__ unsigned long long dup2(float w) {
    unsigned long long r;
    unsigned int u = __float_as_uint(w);
    asm("mov.b64 %0, {%1, %1};" : "=l"(r) : "r"(u));
    return r;
}
__device__ __forceinline__ float2 unpk(unsigned long long v) {
    unsigned int lo, hi;
    asm("mov.b64 {%0, %1}, %2;" : "=r"(lo), "=r"(hi) : "l"(v));
    return make_float2(__uint_as_float(lo), __uint_as_float(hi));
}

// ---------------- fast, accurate-enough nonlinearities ----------------
__device__ __forceinline__ float sigm(float x) {
    return __fdividef(1.0f, 1.0f + __expf(-x));
}
__device__ __forceinline__ float tanhfast(float x) {
    // 2*sigmoid(2x)-1 ; __expf handles +-inf saturation correctly
    return __fdividef(2.0f, 1.0f + __expf(-2.0f * x)) - 1.0f;
}

// ---------------- pre-kernel: transpose weights ----------------
__global__ void transpose_kernel(const float* __restrict__ W_hh,
                                 const float* __restrict__ W_out) {
    int idx = blockIdx.x * blockDim.x + threadIdx.x;
    int stride = gridDim.x * blockDim.x;
    for (int i = idx; i < HDIM * TH; i += stride) {
        int k = i / TH, j = i - k * TH;
        g_Wt[i] = W_hh[j * HDIM + k];
    }
    for (int i = idx; i < HDIM * POUT; i += stride) {
        int k = i / POUT, p = i - k * POUT;
        g_WoutT[i] = W_out[p * HDIM + k];
    }
}

// ---------------- gate epilogue per (row, hidden-unit) ----------------
__device__ __forceinline__ void gate_update(
    float a_r, float a_z, float a_n, float xval,
    float wir, float wiz, float win,
    float bir, float biz, float bin,
    float bhr, float bhz, float bhn,
    const float* __restrict__ hcp, float* __restrict__ hnp)
{
    float rg = sigm(fmaf(xval, wir, bir) + a_r + bhr);
    float zg = sigm(fmaf(xval, wiz, biz) + a_z + bhz);
    float ng = tanhfast(fmaf(xval, win, bin) + rg * (a_n + bhn));
    float hold = *hcp;
    *hnp = ng + zg * (hold - ng);
}

// ---------------- main persistent GRU kernel ----------------
__global__ void __launch_bounds__(NTHREADS, 1)
gru_kernel(const float* __restrict__ x,
           const float* __restrict__ W_ih,
           const float* __restrict__ b_ih,
           const float* __restrict__ b_hh,
           const float* __restrict__ b_out,
           float* __restrict__ out)
{
    extern __shared__ float sm[];
    // layout: [hbuf0 | hbuf1 | wih(768) | bih(768) | bhh(768)]
    float* s_wih = sm + 2 * HBUF;
    float* s_bih = s_wih + TH;
    float* s_bhh = s_bih + TH;

    const int tid  = threadIdx.x;
    const int wid  = tid >> 5;
    const int lane = tid & 31;
    const int r0   = wid * ROWS_PER_WARP;            // local row base
    const int grow = blockIdx.x * TILE_B + r0;       // global row base

    for (int i = tid; i < TH; i += NTHREADS) {
        s_wih[i] = W_ih[i];
        s_bih[i] = b_ih[i];
        s_bhh[i] = b_hh[i];
    }
    for (int i = tid; i < HBUF; i += NTHREADS) sm[i] = 0.0f;  // h0 = 0
    __syncthreads();

    for (int t = 0; t < SEQ; ++t) {
        float* hc = sm + ((t & 1) ? HBUF : 0);   // source (old h)
        float* hn = sm + ((t & 1) ? 0 : HBUF);   // destination (new h)

        // x scalar per row for this step (L1-resident along t)
        float xv[ROWS_PER_WARP];
        #pragma unroll
        for (int i = 0; i < ROWS_PER_WARP; ++i)
            xv[i] = x[(grow + i) * SEQ + t];

        #pragma unroll
        for (int pass = 0; pass < 2; ++pass) {
            const int jb = (pass * 32 + lane) * 4;   // this thread's 4 hidden cols

            // acc[pair][gate][jj] : f32x2 accumulators, rows packed in pairs
            unsigned long long acc[4][3][4];
            #pragma unroll
            for (int a = 0; a < 4; ++a)
                #pragma unroll
                for (int g = 0; g < 3; ++g)
                    #pragma unroll
                    for (int c = 0; c < 4; ++c) acc[a][g][c] = 0ull;

            #pragma unroll 4
            for (int k = 0; k < HDIM; ++k) {
                const ulonglong2* hp =
                    reinterpret_cast<const ulonglong2*>(hc + k * HSTR + r0);
                ulonglong2 hv01 = hp[0];   // rows r0..r0+3 (pairs 0,1)
                ulonglong2 hv23 = hp[1];   // rows r0+4..r0+7 (pairs 2,3)
                const float* wk = g_Wt + k * TH + jb;
                #pragma unroll
                for (int g = 0; g < 3; ++g) {
                    float4 wv = *reinterpret_cast<const float4*>(wk + g * HDIM);
                    unsigned long long w0 = dup2(wv.x);
                    unsigned long long w1 = dup2(wv.y);
                    unsigned long long w2 = dup2(wv.z);
                    unsigned long long w3 = dup2(wv.w);
                    fma2(acc[0][g][0], hv01.x, w0); fma2(acc[1][g][0], hv01.y, w0);
                    fma2(acc[2][g][0], hv23.x, w0); fma2(acc[3][g][0], hv23.y, w0);
                    fma2(acc[0][g][1], hv01.x, w1); fma2(acc[1][g][1], hv01.y, w1);
                    fma2(acc[2][g][1], hv23.x, w1); fma2(acc[3][g][1], hv23.y, w1);
                    fma2(acc[0][g][2], hv01.x, w2); fma2(acc[1][g][2], hv01.y, w2);
                    fma2(acc[2][g][2], hv23.x, w2); fma2(acc[3][g][2], hv23.y, w2);
                    fma2(acc[0][g][3], hv01.x, w3); fma2(acc[1][g][3], hv01.y, w3);
                    fma2(acc[2][g][3], hv23.x, w3); fma2(acc[3][g][3], hv23.y, w3);
                }
            }

            // gates + h update for this pass's 4 cols x 8 rows
            #pragma unroll
            for (int jj = 0; jj < 4; ++jj) {
                const int j = jb + jj;
                const float bhr = s_bhh[j];
                const float bhz = s_bhh[HDIM + j];
                const float bhn = s_bhh[2 * HDIM + j];
                const float wir = s_wih[j];
                const float wiz = s_wih[HDIM + j];
                const float win = s_wih[2 * HDIM + j];
                const float bir = s_bih[j];
                const float biz = s_bih[HDIM + j];
                const float bin = s_bih[2 * HDIM + j];
                #pragma unroll
                for (int pr = 0; pr < 4; ++pr) {
                    float2 ar = unpk(acc[pr][0][jj]);
                    float2 az = unpk(acc[pr][1][jj]);
                    float2 an = unpk(acc[pr][2][jj]);
                    const int i0 = pr * 2;
                    gate_update(ar.x, az.x, an.x, xv[i0],
                                wir, wiz, win, bir, biz, bin, bhr, bhz, bhn,
                                hc + j * HSTR + r0 + i0,
                                hn + j * HSTR + r0 + i0);
                    gate_update(ar.y, az.y, an.y, xv[i0 + 1],
                                wir, wiz, win, bir, biz, bin, bhr, bhz, bhn,
                                hc + j * HSTR + r0 + i0 + 1,
                                hn + j * HSTR + r0 + i0 + 1);
                }
            }
        }
        __syncthreads();  // all writes to hn done before next step reads it
    }

    // SEQ is even -> final h lives in buffer 0
    const float* hfin = sm;

    // out[b][p] = sum_k h[b][k] * W_out[p][k] + b_out[p]; lane -> {p, p+32, p+64}
    float oacc[ROWS_PER_WARP][3];
    #pragma unroll
    for (int i = 0; i < ROWS_PER_WARP; ++i)
        oacc[i][0] = oacc[i][1] = oacc[i][2] = 0.0f;

    for (int k = 0; k < HDIM; ++k) {
        const float w0 = g_WoutT[k * POUT + lane];
        const float w1 = g_WoutT[k * POUT + lane + 32];
        const float w2 = g_WoutT[k * POUT + lane + 64];
        #pragma unroll
        for (int i = 0; i < ROWS_PER_WARP; ++i) {
            const float hv = hfin[k * HSTR + r0 + i];
            oacc[i][0] = fmaf(hv, w0, oacc[i][0]);
            oacc[i][1] = fmaf(hv, w1, oacc[i][1]);
            oacc[i][2] = fmaf(hv, w2, oacc[i][2]);
        }
    }
    const float bo0 = b_out[lane];
    const float bo1 = b_out[lane + 32];
    const float bo2 = b_out[lane + 64];
    #pragma unroll
    for (int i = 0; i < ROWS_PER_WARP; ++i) {
        float* op = out + (size_t)(grow + i) * POUT;
        op[lane]      = oacc[i][0] + bo0;
        op[lane + 32] = oacc[i][1] + bo1;
        op[lane + 64] = oacc[i][2] + bo2;
    }
}

extern "C" void kernel_launch(void* const* d_in, const int* in_sizes, int n_in,
                              void* d_out, int out_size) {
    const float* x     = (const float*)d_in[0];
    const float* W_ih  = (const float*)d_in[1];
    const float* W_hh  = (const float*)d_in[2];
    const float* b_ih  = (const float*)d_in[3];
    const float* b_hh  = (const float*)d_in[4];
    const float* W_out = (const float*)d_in[5];
    const float* b_out = (const float*)d_in[6];
    float* out = (float*)d_out;

    const size_t smem = (size_t)(2 * HBUF + 3 * TH) * sizeof(float); // ~157 KB
    cudaFuncSetAttribute(gru_kernel,
                         cudaFuncAttributeMaxDynamicSharedMemorySize, (int)smem);

    transpose_kernel<<<256, 256>>>(W_hh, W_out);
    gru_kernel<<<NCTA, NTHREADS, smem>>>(x, W_ih, b_ih, b_hh, b_out, out);
}